// round 13
// baseline (speedup 1.0000x reference)
#include <cuda_runtime.h>
#include <cuda_bf16.h>
#include <cstdint>

// Problem constants (from reference):
//   R_MAX=32, S_MAX=2 -> C_R = 66, C_S = 6, DIM_PAIR = 128
//   W rows: [0,66) = W_si, [66,132) = W_ti, 132 = w_ent, [133,139) = W_sym
//
// Session-established optimum (rounds 1-12):
//   * one pair per warp per step, warp-interleaved pair order (contiguous
//     chip-wide write window; wider windows regress 25-50%)
//   * STG.128 + .cs (.wb/.wt -10us, 256-bit -35..47us)
//   * __ldg per-pair scalar loads beat smem-key variants
//   * 304 CTAs x 1024 (all 152 SMs, 2/SM): 88.58us, DRAM 69.2%
// This round: SINGLE change — kill the per-pair 64-bit divide (p/L) with a
// branch-free incremental (i,j) update. ALU was 65.2%, issue 81.5%.
#define DIM 128
#define NCTA 304

__global__ __launch_bounds__(1024, 2)
void rpe_kernel(const int* __restrict__ seq_index,
                const int* __restrict__ seq_color,
                const int* __restrict__ seq_sym,
                const int* __restrict__ seq_entity,
                const int* __restrict__ token_index,
                const float* __restrict__ W,
                float* __restrict__ out,
                int L)
{
    // Shared tables:
    //   T1[d][k]   = W_si[d][k] + W_ti[65][k]      (66 rows) — d_ti==65 fast path folded
    //   Wsym[d][k] = W_sym[d][k] + (d!=5)*w_ent[k] (6 rows)  — bij_entity <=> d_sym!=5
    __shared__ float sT1[66 * DIM];
    __shared__ float sSym[6 * DIM];

    const int tid = threadIdx.x;

    for (int idx = tid; idx < 66 * DIM; idx += blockDim.x) {
        int k = idx & (DIM - 1);
        sT1[idx] = W[idx] + W[131 * DIM + k];
    }
    for (int idx = tid; idx < 6 * DIM; idx += blockDim.x) {
        int d = idx >> 7, k = idx & (DIM - 1);
        float v = W[(133 + d) * DIM + k];
        if (d != 5) v += W[132 * DIM + k];
        sSym[idx] = v;
    }
    __syncthreads();

    const int lane = tid & 31;
    const int warp = tid >> 5;

    // Register-cached hot rows (i-independent):
    const float4 base = *reinterpret_cast<const float4*>(sT1  + 65 * DIM + lane * 4);
    const float4 sym5 = *reinterpret_cast<const float4*>(sSym + 5 * DIM  + lane * 4);
    const float4 hot  = make_float4(base.x + sym5.x, base.y + sym5.y,
                                    base.z + sym5.z, base.w + sym5.w);

    // Persistent warps grid-stride over the flattened pair space.
    // Incremental (i,j) bookkeeping: the divide runs ONCE per warp here,
    // not once per pair (was ~20+ ALU ops/pair at issue=81.5%).
    const int npairs      = L * L;                          // 2^20: fits int
    const int total_warps = gridDim.x * (blockDim.x >> 5);  // 9728
    const int gwarp       = blockIdx.x * (blockDim.x >> 5) + warp;

    const int step_i = total_warps / L;
    const int step_j = total_warps - step_i * L;

    int p = gwarp;
    int i = p / L;                                          // once
    int j = p - i * L;

    float4* __restrict__ dst =
        reinterpret_cast<float4*>(out) + (size_t)p * (DIM / 4) + lane;
    const int dst_step = total_warps * (DIM / 4);

    while (p < npairs) {
        const int sc_i = __ldg(seq_color  + i);
        const int se_i = __ldg(seq_entity + i);
        const int scj  = __ldg(seq_color  + j);
        const int sej  = __ldg(seq_entity + j);
        const bool bc = (sc_i == scj);
        const bool be = (se_i == sej);

        float4 v;
        if (!bc && !be) {
            v = hot;                                   // ~56% of pairs: zero table reads
        } else {
            if (bc) {
                const int si_i = __ldg(seq_index + i);
                const int sij  = __ldg(seq_index + j);
                int d = min(max(si_i - sij, -32), 32) + 32;
                v = *reinterpret_cast<const float4*>(sT1 + d * DIM + lane * 4);
                if (si_i == sij) {
                    // very rare (~0.1%): real token-index bin; add W_ti[d_ti]-W_ti[65] from gmem
                    const int ti_i = __ldg(token_index + i);
                    const int tij  = __ldg(token_index + j);
                    int dt = min(max(ti_i - tij, -32), 32) + 32;
                    float4 wt  = __ldg(reinterpret_cast<const float4*>(W + (66 + dt) * DIM + lane * 4));
                    float4 w65 = __ldg(reinterpret_cast<const float4*>(W + 131 * DIM       + lane * 4));
                    v.x += wt.x - w65.x; v.y += wt.y - w65.y;
                    v.z += wt.z - w65.z; v.w += wt.w - w65.w;
                }
            } else {
                v = base;
            }
            float4 s;
            if (be) {
                const int ss_i = __ldg(seq_sym + i);
                const int ssj  = __ldg(seq_sym + j);
                int ds = min(max(ss_i - ssj, -2), 2) + 2;
                s = *reinterpret_cast<const float4*>(sSym + ds * DIM + lane * 4);
            } else {
                s = sym5;
            }
            v.x += s.x; v.y += s.y; v.z += s.z; v.w += s.w;
        }

        // streaming store: output is write-once, never re-read -> don't pollute L2
        __stcs(dst, v);

        // advance one grid-stride step — branch-free 32-bit index update
        p   += total_warps;
        dst += dst_step;
        j   += step_j;
        int wrap = (j >= L);
        i   += step_i + wrap;
        j   -= wrap ? L : 0;
    }
}

extern "C" void kernel_launch(void* const* d_in, const int* in_sizes, int n_in,
                              void* d_out, int out_size)
{
    const int* seq_index   = (const int*)d_in[0];
    const int* seq_color   = (const int*)d_in[1];
    const int* seq_sym     = (const int*)d_in[2];
    const int* seq_entity  = (const int*)d_in[3];
    const int* token_index = (const int*)d_in[4];
    const float* W         = (const float*)d_in[5];
    float* out             = (float*)d_out;

    const int L = in_sizes[0];   // 1024 (B=1)

    rpe_kernel<<<NCTA, 1024>>>(seq_index, seq_color, seq_sym, seq_entity,
                               token_index, W, out, L);
}

// round 14
// speedup vs baseline: 1.0385x; 1.0385x over previous
#include <cuda_runtime.h>
#include <cuda_bf16.h>
#include <cstdint>

// Problem constants (from reference):
//   R_MAX=32, S_MAX=2 -> C_R = 66, C_S = 6, DIM_PAIR = 128
//   W rows: [0,66) = W_si, [66,132) = W_ti, 132 = w_ent, [133,139) = W_sym
//
// Session-established optimum (rounds 1-13):
//   * one pair per warp per step, warp-interleaved pair order
//   * per-iteration indices computed INDEPENDENTLY from p (enables
//     cross-iteration pipelining; incremental chains regressed 3x)
//   * STG.128 + .cs ; __ldg scalars ; 304 CTAs x 1024 (152 SMs, 2/SM)
//   -> champion 88.58us, DRAM 69.2%, issue 81.5%
// This round: specialize L=2^k so i=p>>k, j=p&(L-1) — keeps independence,
// removes the per-pair 64-bit divide (~20 ALU ops at issue 81.5%).
#define DIM 128
#define NCTA 304

template<bool POW2>
__global__ __launch_bounds__(1024, 2)
void rpe_kernel(const int* __restrict__ seq_index,
                const int* __restrict__ seq_color,
                const int* __restrict__ seq_sym,
                const int* __restrict__ seq_entity,
                const int* __restrict__ token_index,
                const float* __restrict__ W,
                float* __restrict__ out,
                int L, int logL)
{
    // Shared tables:
    //   T1[d][k]   = W_si[d][k] + W_ti[65][k]      (66 rows) — d_ti==65 fast path folded
    //   Wsym[d][k] = W_sym[d][k] + (d!=5)*w_ent[k] (6 rows)  — bij_entity <=> d_sym!=5
    __shared__ float sT1[66 * DIM];
    __shared__ float sSym[6 * DIM];

    const int tid = threadIdx.x;

    for (int idx = tid; idx < 66 * DIM; idx += blockDim.x) {
        int k = idx & (DIM - 1);
        sT1[idx] = W[idx] + W[131 * DIM + k];
    }
    for (int idx = tid; idx < 6 * DIM; idx += blockDim.x) {
        int d = idx >> 7, k = idx & (DIM - 1);
        float v = W[(133 + d) * DIM + k];
        if (d != 5) v += W[132 * DIM + k];
        sSym[idx] = v;
    }
    __syncthreads();

    const int lane = tid & 31;
    const int warp = tid >> 5;

    // Register-cached hot rows (i-independent):
    const float4 base = *reinterpret_cast<const float4*>(sT1  + 65 * DIM + lane * 4);
    const float4 sym5 = *reinterpret_cast<const float4*>(sSym + 5 * DIM  + lane * 4);
    const float4 hot  = make_float4(base.x + sym5.x, base.y + sym5.y,
                                    base.z + sym5.z, base.w + sym5.w);

    // Persistent warps grid-stride over the flattened pair space.
    // Indices recomputed independently from p each iteration (keeps
    // cross-iteration ILP); POW2 path does it with shift/mask.
    const long long npairs      = (long long)L * (long long)L;
    const int       total_warps = gridDim.x * (blockDim.x >> 5);
    const int       gwarp       = blockIdx.x * (blockDim.x >> 5) + warp;

    float4* __restrict__ out4 = reinterpret_cast<float4*>(out);

    for (long long p = gwarp; p < npairs; p += total_warps) {
        int i, j;
        if (POW2) {
            i = (int)(p >> logL);
            j = (int)p & (L - 1);
        } else {
            i = (int)(p / L);
            j = (int)(p - (long long)i * L);
        }

        const int sc_i = __ldg(seq_color  + i);
        const int se_i = __ldg(seq_entity + i);
        const int scj  = __ldg(seq_color  + j);
        const int sej  = __ldg(seq_entity + j);
        const bool bc = (sc_i == scj);
        const bool be = (se_i == sej);

        float4 v;
        if (!bc && !be) {
            v = hot;                                   // ~56% of pairs: zero table reads
        } else {
            if (bc) {
                const int si_i = __ldg(seq_index + i);
                const int sij  = __ldg(seq_index + j);
                int d = min(max(si_i - sij, -32), 32) + 32;
                v = *reinterpret_cast<const float4*>(sT1 + d * DIM + lane * 4);
                if (si_i == sij) {
                    // very rare (~0.1%): real token-index bin; add W_ti[d_ti]-W_ti[65] from gmem
                    const int ti_i = __ldg(token_index + i);
                    const int tij  = __ldg(token_index + j);
                    int dt = min(max(ti_i - tij, -32), 32) + 32;
                    float4 wt  = __ldg(reinterpret_cast<const float4*>(W + (66 + dt) * DIM + lane * 4));
                    float4 w65 = __ldg(reinterpret_cast<const float4*>(W + 131 * DIM       + lane * 4));
                    v.x += wt.x - w65.x; v.y += wt.y - w65.y;
                    v.z += wt.z - w65.z; v.w += wt.w - w65.w;
                }
            } else {
                v = base;
            }
            float4 s;
            if (be) {
                const int ss_i = __ldg(seq_sym + i);
                const int ssj  = __ldg(seq_sym + j);
                int ds = min(max(ss_i - ssj, -2), 2) + 2;
                s = *reinterpret_cast<const float4*>(sSym + ds * DIM + lane * 4);
            } else {
                s = sym5;
            }
            v.x += s.x; v.y += s.y; v.z += s.z; v.w += s.w;
        }

        // streaming store: output is write-once, never re-read -> don't pollute L2
        __stcs(out4 + p * (DIM / 4) + lane, v);
    }
}

extern "C" void kernel_launch(void* const* d_in, const int* in_sizes, int n_in,
                              void* d_out, int out_size)
{
    const int* seq_index   = (const int*)d_in[0];
    const int* seq_color   = (const int*)d_in[1];
    const int* seq_sym     = (const int*)d_in[2];
    const int* seq_entity  = (const int*)d_in[3];
    const int* token_index = (const int*)d_in[4];
    const float* W         = (const float*)d_in[5];
    float* out             = (float*)d_out;

    const int L = in_sizes[0];   // 1024 (B=1)

    if ((L & (L - 1)) == 0) {
        int logL = 0;
        while ((1 << logL) < L) logL++;
        rpe_kernel<true><<<NCTA, 1024>>>(seq_index, seq_color, seq_sym,
                                         seq_entity, token_index, W, out, L, logL);
    } else {
        rpe_kernel<false><<<NCTA, 1024>>>(seq_index, seq_color, seq_sym,
                                          seq_entity, token_index, W, out, L, 0);
    }
}

// round 15
// speedup vs baseline: 1.0479x; 1.0091x over previous
#include <cuda_runtime.h>
#include <cuda_bf16.h>
#include <cstdint>

// Problem constants (from reference):
//   R_MAX=32, S_MAX=2 -> C_R = 66, C_S = 6, DIM_PAIR = 128
//   W rows: [0,66) = W_si, [66,132) = W_ti, 132 = w_ent, [133,139) = W_sym
//
// FINAL: session-converged optimum (rounds 1-14 evidence):
//   * one pair per warp per step, warp-interleaved pair order — contiguous
//     chip-wide instantaneous write window (~4.8MB); any widening (2x/16x)
//     regressed 25-50%
//   * per-iteration indices computed independently from p (cross-iteration
//     store pipelining; chained incremental indexing regressed in 3 trials)
//   * STG.128 + .cs  (.wb -10us, .wt -10us, 256-bit -35..47us)
//   * __ldg per-pair scalars (beat smem-key variants)
//   * 304 CTAs x 1024 threads = all 152 SMs at 2 CTAs/SM (296 left a tail)
//   -> 88.58us, DRAM 69.2%, ~5.8 TB/s effective write BW: the HBM3e
//      pure-write ceiling for this 512MB write-once output. Issue pressure
//      proven non-binding across 55-82% (R14 A/B).
#define DIM 128
#define NCTA 304

__global__ __launch_bounds__(1024, 2)
void rpe_kernel(const int* __restrict__ seq_index,
                const int* __restrict__ seq_color,
                const int* __restrict__ seq_sym,
                const int* __restrict__ seq_entity,
                const int* __restrict__ token_index,
                const float* __restrict__ W,
                float* __restrict__ out,
                int L)
{
    // Shared tables:
    //   T1[d][k]   = W_si[d][k] + W_ti[65][k]      (66 rows) — d_ti==65 fast path folded
    //   Wsym[d][k] = W_sym[d][k] + (d!=5)*w_ent[k] (6 rows)  — bij_entity <=> d_sym!=5
    __shared__ float sT1[66 * DIM];
    __shared__ float sSym[6 * DIM];

    const int tid = threadIdx.x;

    for (int idx = tid; idx < 66 * DIM; idx += blockDim.x) {
        int k = idx & (DIM - 1);
        sT1[idx] = W[idx] + W[131 * DIM + k];
    }
    for (int idx = tid; idx < 6 * DIM; idx += blockDim.x) {
        int d = idx >> 7, k = idx & (DIM - 1);
        float v = W[(133 + d) * DIM + k];
        if (d != 5) v += W[132 * DIM + k];
        sSym[idx] = v;
    }
    __syncthreads();

    const int lane = tid & 31;
    const int warp = tid >> 5;

    // Register-cached hot rows (i-independent):
    const float4 base = *reinterpret_cast<const float4*>(sT1  + 65 * DIM + lane * 4);
    const float4 sym5 = *reinterpret_cast<const float4*>(sSym + 5 * DIM  + lane * 4);
    const float4 hot  = make_float4(base.x + sym5.x, base.y + sym5.y,
                                    base.z + sym5.z, base.w + sym5.w);

    // Persistent warps grid-stride over the flattened pair space.
    const long long npairs      = (long long)L * (long long)L;
    const int       total_warps = gridDim.x * (blockDim.x >> 5);
    const int       gwarp       = blockIdx.x * (blockDim.x >> 5) + warp;

    float4* __restrict__ out4 = reinterpret_cast<float4*>(out);

    for (long long p = gwarp; p < npairs; p += total_warps) {
        const int i = (int)(p / L);
        const int j = (int)(p - (long long)i * L);

        const int sc_i = __ldg(seq_color  + i);
        const int se_i = __ldg(seq_entity + i);
        const int scj  = __ldg(seq_color  + j);
        const int sej  = __ldg(seq_entity + j);
        const bool bc = (sc_i == scj);
        const bool be = (se_i == sej);

        float4 v;
        if (!bc && !be) {
            v = hot;                                   // ~56% of pairs: zero table reads
        } else {
            if (bc) {
                const int si_i = __ldg(seq_index + i);
                const int sij  = __ldg(seq_index + j);
                int d = min(max(si_i - sij, -32), 32) + 32;
                v = *reinterpret_cast<const float4*>(sT1 + d * DIM + lane * 4);
                if (si_i == sij) {
                    // very rare (~0.1%): real token-index bin; add W_ti[d_ti]-W_ti[65] from gmem
                    const int ti_i = __ldg(token_index + i);
                    const int tij  = __ldg(token_index + j);
                    int dt = min(max(ti_i - tij, -32), 32) + 32;
                    float4 wt  = __ldg(reinterpret_cast<const float4*>(W + (66 + dt) * DIM + lane * 4));
                    float4 w65 = __ldg(reinterpret_cast<const float4*>(W + 131 * DIM       + lane * 4));
                    v.x += wt.x - w65.x; v.y += wt.y - w65.y;
                    v.z += wt.z - w65.z; v.w += wt.w - w65.w;
                }
            } else {
                v = base;
            }
            float4 s;
            if (be) {
                const int ss_i = __ldg(seq_sym + i);
                const int ssj  = __ldg(seq_sym + j);
                int ds = min(max(ss_i - ssj, -2), 2) + 2;
                s = *reinterpret_cast<const float4*>(sSym + ds * DIM + lane * 4);
            } else {
                s = sym5;
            }
            v.x += s.x; v.y += s.y; v.z += s.z; v.w += s.w;
        }

        // streaming store: output is write-once, never re-read -> don't pollute L2
        __stcs(out4 + p * (DIM / 4) + lane, v);
    }
}

extern "C" void kernel_launch(void* const* d_in, const int* in_sizes, int n_in,
                              void* d_out, int out_size)
{
    const int* seq_index   = (const int*)d_in[0];
    const int* seq_color   = (const int*)d_in[1];
    const int* seq_sym     = (const int*)d_in[2];
    const int* seq_entity  = (const int*)d_in[3];
    const int* token_index = (const int*)d_in[4];
    const float* W         = (const float*)d_in[5];
    float* out             = (float*)d_out;

    const int L = in_sizes[0];   // 1024 (B=1)

    rpe_kernel<<<NCTA, 1024>>>(seq_index, seq_color, seq_sym, seq_entity,
                               token_index, W, out, L);
}